// round 4
// baseline (speedup 1.0000x reference)
#include <cuda_runtime.h>

// x[256, 4096, 32] -> out[256, 64, 64, 32]  (GADF)
#define BATCH 256
#define TLEN  4096
#define CH    32
#define PAA   64
#define BINSZ 64   // TLEN / PAA
#define SEGS  8    // segments per batch in reduce kernel

// Inter-kernel scratch (small; L2-resident).
__device__ float g_binsum[BATCH][PAA][CH];       // 2 MB
__device__ float g_pmin[BATCH][SEGS][CH];        // 256 KB
__device__ float g_pmax[BATCH][SEGS][CH];        // 256 KB

// ---------------------------------------------------------------------------
// K1: pure read stream. 2048 blocks x 256 threads.
// Block -> (b = blk>>3, seg s = blk&7) covering t in [512s, 512s+512).
// Warp w (0..7) reduces exactly bin 8s+w (64 t-rows).
// lane -> (t_off = lane>>3 in [0,4), c4 = (lane&7)*4); 16 x LDG.128 per lane.
// ---------------------------------------------------------------------------
__global__ __launch_bounds__(256)
void gaf_reduce_kernel(const float* __restrict__ x) {
    __shared__ float smn[8][36];
    __shared__ float smx[8][36];

    const int tid   = threadIdx.x;
    const int lane  = tid & 31;
    const int warp  = tid >> 5;          // 0..7
    const int t_off = lane >> 3;         // 0..3
    const int c4    = (lane & 7) * 4;
    const int b     = blockIdx.x >> 3;
    const int s     = blockIdx.x & 7;
    const int bin   = 8 * s + warp;

    const float* base = x + (size_t)b * (TLEN * CH)
                          + (size_t)(bin * BINSZ + t_off) * CH + c4;

    float4 sum  = {0, 0, 0, 0};
    float4 vmin = { 3.4e38f,  3.4e38f,  3.4e38f,  3.4e38f};
    float4 vmax = {-3.4e38f, -3.4e38f, -3.4e38f, -3.4e38f};

    #pragma unroll
    for (int k = 0; k < 16; ++k) {
        float4 v = __ldcs((const float4*)(base + (size_t)(4 * k) * CH));
        sum.x += v.x; sum.y += v.y; sum.z += v.z; sum.w += v.w;
        vmin.x = fminf(vmin.x, v.x); vmin.y = fminf(vmin.y, v.y);
        vmin.z = fminf(vmin.z, v.z); vmin.w = fminf(vmin.w, v.w);
        vmax.x = fmaxf(vmax.x, v.x); vmax.y = fmaxf(vmax.y, v.y);
        vmax.z = fmaxf(vmax.z, v.z); vmax.w = fmaxf(vmax.w, v.w);
    }

    // Collapse the 4 t_off copies (lanes xor 8, 16).
    #pragma unroll
    for (int o = 8; o <= 16; o <<= 1) {
        sum.x += __shfl_xor_sync(~0u, sum.x, o); sum.y += __shfl_xor_sync(~0u, sum.y, o);
        sum.z += __shfl_xor_sync(~0u, sum.z, o); sum.w += __shfl_xor_sync(~0u, sum.w, o);
        vmin.x = fminf(vmin.x, __shfl_xor_sync(~0u, vmin.x, o));
        vmin.y = fminf(vmin.y, __shfl_xor_sync(~0u, vmin.y, o));
        vmin.z = fminf(vmin.z, __shfl_xor_sync(~0u, vmin.z, o));
        vmin.w = fminf(vmin.w, __shfl_xor_sync(~0u, vmin.w, o));
        vmax.x = fmaxf(vmax.x, __shfl_xor_sync(~0u, vmax.x, o));
        vmax.y = fmaxf(vmax.y, __shfl_xor_sync(~0u, vmax.y, o));
        vmax.z = fmaxf(vmax.z, __shfl_xor_sync(~0u, vmax.z, o));
        vmax.w = fmaxf(vmax.w, __shfl_xor_sync(~0u, vmax.w, o));
    }

    if (t_off == 0) {  // lanes 0..7: channels c4..c4+3
        *(float4*)&g_binsum[b][bin][c4] = sum;
        *(float4*)&smn[warp][c4] = vmin;
        *(float4*)&smx[warp][c4] = vmax;
    }
    __syncthreads();

    if (tid < CH) {
        float m = smn[0][tid], M = smx[0][tid];
        #pragma unroll
        for (int w = 1; w < 8; ++w) {
            m = fminf(m, smn[w][tid]);
            M = fmaxf(M, smx[w][tid]);
        }
        g_pmin[b][s][tid] = m;
        g_pmax[b][s][tid] = M;
    }
}

// ---------------------------------------------------------------------------
// K2: pure write stream. 2048 blocks x 256 threads.
// Block -> (b = blk>>3, i-chunk ic = blk&7 covering i in [8ic, 8ic+8)).
// Builds p,y in SMEM from L2-resident scratch, then writes 64 KB:
//   out[b,i,j,c] = y_i*p_j - p_i*y_j, STG.128, 512B contiguous per warp.
// ---------------------------------------------------------------------------
__global__ __launch_bounds__(256)
void gaf_produce_kernel(float* __restrict__ out) {
    __shared__ float sp[PAA][CH];    // p
    __shared__ float sy[PAA][CH];    // y
    __shared__ float smin[CH];
    __shared__ float sinv[CH];

    const int tid = threadIdx.x;
    const int b   = blockIdx.x >> 3;
    const int ic  = blockIdx.x & 7;

    if (tid < CH) {
        float m = g_pmin[b][0][tid], M = g_pmax[b][0][tid];
        #pragma unroll
        for (int s = 1; s < SEGS; ++s) {
            m = fminf(m, g_pmin[b][s][tid]);
            M = fmaxf(M, g_pmax[b][s][tid]);
        }
        smin[tid] = m;
        sinv[tid] = 1.0f / (M - m);
    }
    __syncthreads();

    #pragma unroll
    for (int idx = tid; idx < PAA * CH; idx += 256) {
        int c = idx & (CH - 1);
        float pv = ((&g_binsum[b][0][0])[idx] * (1.0f / BINSZ) - smin[c]) * sinv[c];
        (&sp[0][0])[idx] = pv;
        (&sy[0][0])[idx] = sqrtf(fmaxf(0.0f, 1.0f - pv * pv));
    }
    __syncthreads();

    // thread -> (c4 = (tid&7)*4, j0 = tid>>3 in [0,32)); handles j0 and j0+32.
    const int c4 = (tid & 7) * 4;
    const int j0 = tid >> 3;

    const float4 pj0 = *(const float4*)&sp[j0][c4];
    const float4 yj0 = *(const float4*)&sy[j0][c4];
    const float4 pj1 = *(const float4*)&sp[j0 + 32][c4];
    const float4 yj1 = *(const float4*)&sy[j0 + 32][c4];

    float* ob = out + (size_t)b * (PAA * PAA * CH) + c4;
    #pragma unroll
    for (int ii = 0; ii < 8; ++ii) {
        const int i = ic * 8 + ii;
        const float4 pi = *(const float4*)&sp[i][c4];   // 8 addrs, broadcast x4
        const float4 yi = *(const float4*)&sy[i][c4];
        float* orow = ob + (size_t)i * (PAA * CH);

        float4 o0;
        o0.x = yi.x * pj0.x - pi.x * yj0.x;
        o0.y = yi.y * pj0.y - pi.y * yj0.y;
        o0.z = yi.z * pj0.z - pi.z * yj0.z;
        o0.w = yi.w * pj0.w - pi.w * yj0.w;
        __stcs((float4*)(orow + (size_t)j0 * CH), o0);

        float4 o1;
        o1.x = yi.x * pj1.x - pi.x * yj1.x;
        o1.y = yi.y * pj1.y - pi.y * yj1.y;
        o1.z = yi.z * pj1.z - pi.z * yj1.z;
        o1.w = yi.w * pj1.w - pi.w * yj1.w;
        __stcs((float4*)(orow + (size_t)(j0 + 32) * CH), o1);
    }
}

extern "C" void kernel_launch(void* const* d_in, const int* in_sizes, int n_in,
                              void* d_out, int out_size) {
    const float* x = (const float*)d_in[0];
    float* out = (float*)d_out;
    gaf_reduce_kernel<<<BATCH * SEGS, 256>>>(x);
    gaf_produce_kernel<<<BATCH * SEGS, 256>>>(out);
}